// round 10
// baseline (speedup 1.0000x reference)
#include <cuda_runtime.h>
#include <cuda_bf16.h>
#include <cuda_fp16.h>
#include <cstdint>

#define MAXN 50048
#define MAXE 860032
#define IN_DIM 128
#define HEADS 4
#define OUT_DIM 64
#define FTOT 256

// ---------------- scratch ----------------
__device__ unsigned g_hh[(size_t)MAXN * 128];   // h as half2 pairs: 25.6 MB
__device__ float4 g_asrc[MAXN];
__device__ float4 g_adst[MAXN];
__device__ int    g_src[MAXE];
__device__ int    g_cnt[MAXN];
__device__ int    g_off[MAXN + 1];
__device__ int    g_cur[MAXN];
__device__ int    g_bsum[256];
__device__ int    g_boff[256];
__device__ __align__(16) __half g_wt[FTOT * IN_DIM];  // W^T fp16: [n][k]

__device__ __forceinline__ float lrelu(float e) {
    return e > 0.0f ? e : 0.2f * e;
}

__device__ __forceinline__ int edge_stride(const unsigned* w) {
    int is64 = 1;
    #pragma unroll 1
    for (int j = 1; j < 64; j += 2)
        if (w[j] != 0u) { is64 = 0; break; }
    return is64 ? 2 : 1;
}

// ---------------- 1: zero degree counters ----------------
__global__ void zero_cnt_kernel(int N) {
    int i = blockIdx.x * blockDim.x + threadIdx.x;
    if (i < N) g_cnt[i] = 0;
}

// ---------------- 2: histogram ----------------
__global__ void hist_kernel(const unsigned* __restrict__ w, int E, int N) {
    __shared__ int s_st;
    if (threadIdx.x == 0) s_st = edge_stride(w);
    __syncthreads();
    int st = s_st;
    int i = blockIdx.x * blockDim.x + threadIdx.x;
    if (i >= E + N) return;
    int d = (i < E) ? (int)w[st * E + st * i] : (i - E);
    atomicAdd(&g_cnt[d], 1);
}

// ---------------- 3: W transpose -> fp16 ----------------
__global__ void wt_kernel(const float* __restrict__ W) {
    int i = blockIdx.x * 256 + threadIdx.x;     // 0..32767
    int k = i & 127, n = i >> 7;
    g_wt[i] = __float2half_rn(__ldg(W + (size_t)k * FTOT + n));
}

// ---------------- 4: GEMM on fp16 HMMA, all 4 heads per CTA ----------------
// Block: 256 thr (8 warps = 4m x 2n), A tile 128 rows x K=128 filled ONCE,
// then loop over heads re-filling only the 64x128 B tile. acc reused per head.
#define PA 136
#define SM_A 0                                   // 128*136*2 = 34816
#define SM_B 34816                               // 64*136*2 = 17408
#define SM_STG 52224                             // 8 warps * 2560
#define SMEM_BYTES 72704

__global__ void __launch_bounds__(256)
gemm_kernel(const float* __restrict__ x, int N) {
    extern __shared__ __align__(16) char sm[];
    __half* As = (__half*)(sm + SM_A);
    __half* Bs = (__half*)(sm + SM_B);

    const int tid = threadIdx.x;
    const int lane = tid & 31, wid = tid >> 5;
    const int mw = wid & 3, nw = wid >> 2;
    const int m_base = blockIdx.x * 128;

    const int ar = tid >> 3;                    // 0..31 (row group)
    const int ac = tid & 7;                     // vec col idx

    // ---- A fill: 128 rows x 128 k -> fp16, coalesced, once ----
    #pragma unroll
    for (int rr = 0; rr < 4; rr++) {
        int r = ar + rr * 32;
        int grow = m_base + r;
        if (grow >= N) grow = N - 1;
        const float4* xs = (const float4*)(x + (size_t)grow * IN_DIM);
        #pragma unroll
        for (int p = 0; p < 4; p++) {
            float4 v = __ldg(xs + ac + p * 8);
            __half2 h0 = __floats2half2_rn(v.x, v.y);
            __half2 h1 = __floats2half2_rn(v.z, v.w);
            uint2 u;
            u.x = *reinterpret_cast<unsigned*>(&h0);
            u.y = *reinterpret_cast<unsigned*>(&h1);
            *(uint2*)(As + r * PA + (ac + p * 8) * 4) = u;
        }
    }

    const int aoff = (mw * 32 + (lane >> 2)) * PA + (lane & 3) * 2;
    const int boff = (nw * 32 + (lane >> 2)) * PA + (lane & 3) * 2;
    unsigned* stg = (unsigned*)(sm + SM_STG) + wid * (32 * 20);

    #pragma unroll 1
    for (int head = 0; head < HEADS; head++) {
        __syncthreads();                         // Bs free (prev mma done)
        // ---- B fill: 64 n-rows x 128 k for this head ----
        {
            int n = tid >> 2, q = tid & 3;
            const uint4* s = (const uint4*)(g_wt +
                (size_t)(head * OUT_DIM + n) * IN_DIM);
            uint4* dptr = (uint4*)(Bs + n * PA);
            #pragma unroll
            for (int j = 0; j < 4; j++)
                dptr[q * 4 + j] = __ldg(s + q * 4 + j);
        }
        __syncthreads();

        float acc[2][4][4];
        #pragma unroll
        for (int mt = 0; mt < 2; mt++)
            #pragma unroll
            for (int nt = 0; nt < 4; nt++)
                #pragma unroll
                for (int c = 0; c < 4; c++) acc[mt][nt][c] = 0.0f;

        // ---- HMMA over K=128 ----
        #pragma unroll
        for (int kk = 0; kk < 128; kk += 16) {
            unsigned a[2][4], b[4][2];
            #pragma unroll
            for (int mt = 0; mt < 2; mt++) {
                const __half* p = As + aoff + mt * 16 * PA + kk;
                a[mt][0] = *(const unsigned*)(p);
                a[mt][1] = *(const unsigned*)(p + 8 * PA);
                a[mt][2] = *(const unsigned*)(p + 8);
                a[mt][3] = *(const unsigned*)(p + 8 * PA + 8);
            }
            #pragma unroll
            for (int nt = 0; nt < 4; nt++) {
                const __half* p = Bs + boff + nt * 8 * PA + kk;
                b[nt][0] = *(const unsigned*)(p);
                b[nt][1] = *(const unsigned*)(p + 8);
            }
            #pragma unroll
            for (int mt = 0; mt < 2; mt++)
                #pragma unroll
                for (int nt = 0; nt < 4; nt++)
                    asm volatile(
                        "mma.sync.aligned.m16n8k16.row.col.f32.f16.f16.f32 "
                        "{%0,%1,%2,%3}, {%4,%5,%6,%7}, {%8,%9}, {%0,%1,%2,%3};"
                        : "+f"(acc[mt][nt][0]), "+f"(acc[mt][nt][1]),
                          "+f"(acc[mt][nt][2]), "+f"(acc[mt][nt][3])
                        : "r"(a[mt][0]), "r"(a[mt][1]), "r"(a[mt][2]), "r"(a[mt][3]),
                          "r"(b[nt][0]), "r"(b[nt][1]));
        }

        // ---- epilogue: per-warp half2 staging -> coalesced g_hh stores ----
        #pragma unroll
        for (int mt = 0; mt < 2; mt++)
            #pragma unroll
            for (int nt = 0; nt < 4; nt++) {
                int rl = mt * 16 + (lane >> 2);
                int cu = nt * 4 + (lane & 3);
                __half2 lo = __floats2half2_rn(acc[mt][nt][0], acc[mt][nt][1]);
                __half2 hi = __floats2half2_rn(acc[mt][nt][2], acc[mt][nt][3]);
                stg[rl * 20 + cu] = *reinterpret_cast<unsigned*>(&lo);
                stg[(rl + 8) * 20 + cu] = *reinterpret_cast<unsigned*>(&hi);
            }
        __syncwarp();
        #pragma unroll
        for (int it = 0; it < 4; it++) {
            int rl = it * 8 + (lane >> 2);
            uint4 v = *(uint4*)(stg + rl * 20 + (lane & 3) * 4);
            int grow = m_base + mw * 32 + rl;
            *(uint4*)(g_hh + (size_t)grow * 128 + head * 32 + nw * 16 +
                      (lane & 3) * 4) = v;
        }
    }
}

// ---------------- 5: att logits from fp16 h (warp per node) ----------------
__global__ void __launch_bounds__(256)
att_kernel(const float* __restrict__ att_src,
           const float* __restrict__ att_dst, int N) {
    int gt = blockIdx.x * blockDim.x + threadIdx.x;
    int node = gt >> 5, lane = gt & 31;
    if (node >= N) return;
    uint4 u = __ldg((const uint4*)(g_hh + (size_t)node * 128) + lane);
    int head = lane >> 3;
    const float4* as4 = (const float4*)(att_src + head * OUT_DIM + (lane & 7) * 8);
    const float4* ad4 = (const float4*)(att_dst + head * OUT_DIM + (lane & 7) * 8);
    float4 a0 = __ldg(as4), a1 = __ldg(as4 + 1);
    float4 d0 = __ldg(ad4), d1 = __ldg(ad4 + 1);
    float2 p0 = __half22float2(*reinterpret_cast<__half2*>(&u.x));
    float2 p1 = __half22float2(*reinterpret_cast<__half2*>(&u.y));
    float2 p2 = __half22float2(*reinterpret_cast<__half2*>(&u.z));
    float2 p3 = __half22float2(*reinterpret_cast<__half2*>(&u.w));
    float s1 = p0.x * a0.x + p0.y * a0.y + p1.x * a0.z + p1.y * a0.w +
               p2.x * a1.x + p2.y * a1.y + p3.x * a1.z + p3.y * a1.w;
    float s2 = p0.x * d0.x + p0.y * d0.y + p1.x * d0.z + p1.y * d0.w +
               p2.x * d1.x + p2.y * d1.y + p3.x * d1.z + p3.y * d1.w;
    #pragma unroll
    for (int off = 4; off >= 1; off >>= 1) {
        s1 += __shfl_xor_sync(0xffffffffu, s1, off);
        s2 += __shfl_xor_sync(0xffffffffu, s2, off);
    }
    if ((lane & 7) == 0) {
        ((float*)&g_asrc[node])[head] = s1;
        ((float*)&g_adst[node])[head] = s2;
    }
}

// ---------------- 6: three-phase exclusive scan ----------------
__global__ void scan_a_kernel(int N) {
    __shared__ int sh[256];
    int idx = blockIdx.x * 256 + threadIdx.x;
    int v = (idx < N) ? g_cnt[idx] : 0;
    sh[threadIdx.x] = v;
    __syncthreads();
    #pragma unroll
    for (int off = 128; off >= 1; off >>= 1) {
        if (threadIdx.x < off) sh[threadIdx.x] += sh[threadIdx.x + off];
        __syncthreads();
    }
    if (threadIdx.x == 0) g_bsum[blockIdx.x] = sh[0];
}

__global__ void scan_b_kernel(int GB) {
    __shared__ int sh[256];
    int t = threadIdx.x;
    int v = (t < GB) ? g_bsum[t] : 0;
    sh[t] = v;
    __syncthreads();
    #pragma unroll
    for (int off = 1; off < 256; off <<= 1) {
        int u = (t >= off) ? sh[t - off] : 0;
        __syncthreads();
        sh[t] += u;
        __syncthreads();
    }
    g_boff[t] = sh[t] - v;
}

__global__ void scan_c_kernel(int N, int ET) {
    __shared__ int sh[256];
    int t = threadIdx.x;
    int idx = blockIdx.x * 256 + t;
    int c = (idx < N) ? g_cnt[idx] : 0;
    sh[t] = c;
    __syncthreads();
    #pragma unroll
    for (int off = 1; off < 256; off <<= 1) {
        int u = (t >= off) ? sh[t - off] : 0;
        __syncthreads();
        sh[t] += u;
        __syncthreads();
    }
    int ex = g_boff[blockIdx.x] + sh[t] - c;
    if (idx < N) {
        g_off[idx] = ex;
        g_cur[idx] = ex;
        if (idx == N - 1) g_off[N] = ET;
    }
}

// ---------------- 7: scatter (CSR fill) ----------------
__global__ void scatter_kernel(const unsigned* __restrict__ w, int E, int N) {
    __shared__ int s_st;
    if (threadIdx.x == 0) s_st = edge_stride(w);
    __syncthreads();
    int st = s_st;
    int i = blockIdx.x * blockDim.x + threadIdx.x;
    if (i >= E + N) return;
    int s, d;
    if (i < E) {
        s = (int)w[st * i];
        d = (int)w[st * E + st * i];
    } else {
        s = d = i - E;
    }
    int pos = atomicAdd(&g_cur[d], 1);
    g_src[pos] = s;
}

// ---------------- 8: fused softmax + aggregate + bias + mix-ELU ------------
__device__ __forceinline__ float mixelu(float z) {
    float e = z > 0.0f ? z : expm1f(z);
    return 0.5f * z + 0.5f * e;
}

__global__ void __launch_bounds__(256)
agg_kernel(float* __restrict__ out, const float* __restrict__ bias, int N) {
    int gt = blockIdx.x * blockDim.x + threadIdx.x;
    int d = gt >> 5;
    int lane = gt & 31;
    if (d >= N) return;
    int beg = g_off[d], end = g_off[d + 1];
    int head = lane >> 3;                        // 8 features per lane
    bool hsel = (head & 1) != 0;
    bool hhi = head >= 2;

    float4 ad4 = g_adst[d];
    float ad = hhi ? (hsel ? ad4.w : ad4.z) : (hsel ? ad4.y : ad4.x);

    float acc[8] = {0.f, 0.f, 0.f, 0.f, 0.f, 0.f, 0.f, 0.f};
    float se = 0.f;

    int j = beg;
    // batched 4-edge iterations: 4 idx loads, then 8 data loads in flight
    #pragma unroll 1
    for (; j + 4 <= end; j += 4) {
        int s[4];
        #pragma unroll
        for (int q = 0; q < 4; q++) s[q] = __ldg(&g_src[j + q]);
        float4 as4[4];
        uint4 u[4];
        #pragma unroll
        for (int q = 0; q < 4; q++) {
            as4[q] = __ldg(&g_asrc[s[q]]);
            u[q] = __ldg((const uint4*)(g_hh + (size_t)s[q] * 128) + lane);
        }
        #pragma unroll
        for (int q = 0; q < 4; q++) {
            float as = hhi ? (hsel ? as4[q].w : as4[q].z)
                           : (hsel ? as4[q].y : as4[q].x);
            float e = __expf(lrelu(as + ad));
            se += e;
            float2 p0 = __half22float2(*reinterpret_cast<__half2*>(&u[q].x));
            float2 p1 = __half22float2(*reinterpret_cast<__half2*>(&u[q].y));
            float2 p2 = __half22float2(*reinterpret_cast<__half2*>(&u[q].z));
            float2 p3 = __half22float2(*reinterpret_cast<__half2*>(&u[q].w));
            acc[0] = fmaf(e, p0.x, acc[0]); acc[1] = fmaf(e, p0.y, acc[1]);
            acc[2] = fmaf(e, p1.x, acc[2]); acc[3] = fmaf(e, p1.y, acc[3]);
            acc[4] = fmaf(e, p2.x, acc[4]); acc[5] = fmaf(e, p2.y, acc[5]);
            acc[6] = fmaf(e, p3.x, acc[6]); acc[7] = fmaf(e, p3.y, acc[7]);
        }
    }
    #pragma unroll 1
    for (; j < end; j++) {
        int s = __ldg(&g_src[j]);
        float4 as4 = __ldg(&g_asrc[s]);
        float as = hhi ? (hsel ? as4.w : as4.z) : (hsel ? as4.y : as4.x);
        float e = __expf(lrelu(as + ad));
        se += e;
        uint4 u = __ldg((const uint4*)(g_hh + (size_t)s * 128) + lane);
        float2 p0 = __half22float2(*reinterpret_cast<__half2*>(&u.x));
        float2 p1 = __half22float2(*reinterpret_cast<__half2*>(&u.y));
        float2 p2 = __half22float2(*reinterpret_cast<__half2*>(&u.z));
        float2 p3 = __half22float2(*reinterpret_cast<__half2*>(&u.w));
        acc[0] = fmaf(e, p0.x, acc[0]); acc[1] = fmaf(e, p0.y, acc[1]);
        acc[2] = fmaf(e, p1.x, acc[2]); acc[3] = fmaf(e, p1.y, acc[3]);
        acc[4] = fmaf(e, p2.x, acc[4]); acc[5] = fmaf(e, p2.y, acc[5]);
        acc[6] = fmaf(e, p3.x, acc[6]); acc[7] = fmaf(e, p3.y, acc[7]);
    }

    float inv = 1.0f / (se + 1e-16f);
    const float* brow = bias + lane * 8;
    float o[8];
    #pragma unroll
    for (int c = 0; c < 8; c++)
        o[c] = mixelu(acc[c] * inv + __ldg(brow + c));

    float4* orow = (float4*)(out + (size_t)d * FTOT);
    orow[lane * 2]     = make_float4(o[0], o[1], o[2], o[3]);
    orow[lane * 2 + 1] = make_float4(o[4], o[5], o[6], o[7]);
}

// ---------------- launch ----------------
extern "C" void kernel_launch(void* const* d_in, const int* in_sizes, int n_in,
                              void* d_out, int out_size) {
    const float*    x       = (const float*)d_in[0];
    const unsigned* edge    = (const unsigned*)d_in[1];
    const float*    W       = (const float*)d_in[2];
    const float*    att_src = (const float*)d_in[3];
    const float*    att_dst = (const float*)d_in[4];
    const float*    bias    = (const float*)d_in[5];
    float*          out     = (float*)d_out;

    const int N = in_sizes[0] / IN_DIM;        // 50000
    const int E = in_sizes[1] / 2;             // 800000
    const int ET = E + N;
    const int GB = (N + 255) / 256;

    cudaFuncSetAttribute(gemm_kernel,
                         cudaFuncAttributeMaxDynamicSharedMemorySize, SMEM_BYTES);

    zero_cnt_kernel<<<(N + 255) / 256, 256>>>(N);                     // 1
    hist_kernel<<<(ET + 255) / 256, 256>>>(edge, E, N);               // 2
    wt_kernel<<<128, 256>>>(W);                                       // 3
    gemm_kernel<<<(N + 127) / 128, 256, SMEM_BYTES>>>(x, N);          // 4 (profiled)
    att_kernel<<<((long)N * 32 + 255) / 256, 256>>>(att_src, att_dst, N); // 5
    scan_a_kernel<<<GB, 256>>>(N);                                    // 6
    scan_b_kernel<<<1, 256>>>(GB);                                    // 7
    scan_c_kernel<<<GB, 256>>>(N, ET);                                // 8
    scatter_kernel<<<(ET + 255) / 256, 256>>>(edge, E, N);            // 9
    agg_kernel<<<((long)N * 32 + 255) / 256, 256>>>(out, bias, N);    // 10
}

// round 11
// speedup vs baseline: 1.1209x; 1.1209x over previous
#include <cuda_runtime.h>
#include <cuda_bf16.h>
#include <cuda_fp16.h>
#include <cstdint>

#define MAXN 50048
#define MAXE 860032
#define IN_DIM 128
#define HEADS 4
#define OUT_DIM 64
#define FTOT 256

// ---------------- scratch ----------------
__device__ unsigned g_hh[(size_t)MAXN * 128];   // h as half2 pairs: 25.6 MB
__device__ float4 g_asrc[MAXN];
__device__ float4 g_adst[MAXN];
__device__ int    g_src[MAXE];
__device__ int    g_cnt[MAXN];
__device__ int    g_off[MAXN + 1];
__device__ int    g_cur[MAXN];
__device__ int    g_bsum[256];
__device__ int    g_boff[256];
__device__ __align__(16) __half g_wt[FTOT * IN_DIM];  // W^T fp16: [n][k]

__device__ __forceinline__ float lrelu(float e) {
    return e > 0.0f ? e : 0.2f * e;
}

__device__ __forceinline__ int edge_stride(const unsigned* w) {
    int is64 = 1;
    #pragma unroll 1
    for (int j = 1; j < 64; j += 2)
        if (w[j] != 0u) { is64 = 0; break; }
    return is64 ? 2 : 1;
}

// ---------------- 1: zero degree counters ----------------
__global__ void zero_cnt_kernel(int N) {
    int i = blockIdx.x * blockDim.x + threadIdx.x;
    if (i < N) g_cnt[i] = 0;
}

// ---------------- 2: histogram (4 edges/thread) ----------------
__global__ void hist_kernel(const unsigned* __restrict__ w, int E, int N) {
    __shared__ int s_st;
    if (threadIdx.x == 0) s_st = edge_stride(w);
    __syncthreads();
    int st = s_st;
    int ET = E + N;
    int base = (blockIdx.x * blockDim.x + threadIdx.x) * 4;
    if (base >= ET) return;
    if (base + 4 <= ET) {
        int d[4];
        #pragma unroll
        for (int q = 0; q < 4; q++) {
            int i = base + q;
            d[q] = (i < E) ? (int)w[st * E + st * i] : (i - E);
        }
        #pragma unroll
        for (int q = 0; q < 4; q++) atomicAdd(&g_cnt[d[q]], 1);
    } else {
        for (int i = base; i < ET; i++) {
            int d = (i < E) ? (int)w[st * E + st * i] : (i - E);
            atomicAdd(&g_cnt[d], 1);
        }
    }
}

// ---------------- 3: W transpose -> fp16 ----------------
__global__ void wt_kernel(const float* __restrict__ W) {
    int i = blockIdx.x * 256 + threadIdx.x;     // 0..32767
    int k = i & 127, n = i >> 7;
    g_wt[i] = __float2half_rn(__ldg(W + (size_t)k * FTOT + n));
}

// ---------------- 4: GEMM on fp16 HMMA, 4 heads/CTA, fused att logits -----
// Block: 256 thr (8 warps = 4m x 2n), A tile 128 x K=128 filled ONCE,
// loop over heads re-filling the 64x128 B tile. Epilogue: fp16 h store +
// att logits from fp32 acc (quad shfl + smem combine across nw warps).
#define PA 136
#define SM_A 0                                   // 34816
#define SM_B 34816                               // 17408 -> 52224
#define SM_STG 52224                             // 8 warps * 2560 -> 72704
#define SM_RED 72704                             // 128*2 floats -> 73728
#define SM_ATTV 73728                            // 512 floats -> 75776
#define SMEM_BYTES 75776

__global__ void __launch_bounds__(256)
gemm_kernel(const float* __restrict__ x,
            const float* __restrict__ att_src,
            const float* __restrict__ att_dst, int N) {
    extern __shared__ __align__(16) char sm[];
    __half* As = (__half*)(sm + SM_A);
    __half* Bs = (__half*)(sm + SM_B);
    float* red_s = (float*)(sm + SM_RED);        // [128]
    float* red_d = red_s + 128;                  // (uses half of ATTV pad? no:)
    float* attv  = (float*)(sm + SM_ATTV);       // [512]: src 0..255, dst 256..

    const int tid = threadIdx.x;
    const int lane = tid & 31, wid = tid >> 5;
    const int mw = wid & 3, nw = wid >> 2;
    const int m_base = blockIdx.x * 128;

    // preload att vectors
    if (tid < 256) {
        attv[tid] = __ldg(att_src + tid);
        attv[256 + tid] = __ldg(att_dst + tid);
    }

    const int ar = tid >> 3;                    // 0..31 (row group)
    const int ac = tid & 7;                     // vec col idx

    // ---- A fill: 128 rows x 128 k -> fp16, coalesced, once ----
    #pragma unroll
    for (int rr = 0; rr < 4; rr++) {
        int r = ar + rr * 32;
        int grow = m_base + r;
        if (grow >= N) grow = N - 1;
        const float4* xs = (const float4*)(x + (size_t)grow * IN_DIM);
        #pragma unroll
        for (int p = 0; p < 4; p++) {
            float4 v = __ldg(xs + ac + p * 8);
            __half2 h0 = __floats2half2_rn(v.x, v.y);
            __half2 h1 = __floats2half2_rn(v.z, v.w);
            uint2 u;
            u.x = *reinterpret_cast<unsigned*>(&h0);
            u.y = *reinterpret_cast<unsigned*>(&h1);
            *(uint2*)(As + r * PA + (ac + p * 8) * 4) = u;
        }
    }

    const int aoff = (mw * 32 + (lane >> 2)) * PA + (lane & 3) * 2;
    const int boff = (nw * 32 + (lane >> 2)) * PA + (lane & 3) * 2;
    unsigned* stg = (unsigned*)(sm + SM_STG) + wid * (32 * 20);

    #pragma unroll 1
    for (int head = 0; head < HEADS; head++) {
        __syncthreads();                         // Bs + red arrays free
        // ---- B fill: 64 n-rows x 128 k for this head ----
        {
            int n = tid >> 2, q = tid & 3;
            const uint4* s = (const uint4*)(g_wt +
                (size_t)(head * OUT_DIM + n) * IN_DIM);
            uint4* dptr = (uint4*)(Bs + n * PA);
            #pragma unroll
            for (int j = 0; j < 4; j++)
                dptr[q * 4 + j] = __ldg(s + q * 4 + j);
        }
        __syncthreads();

        float acc[2][4][4];
        #pragma unroll
        for (int mt = 0; mt < 2; mt++)
            #pragma unroll
            for (int nt = 0; nt < 4; nt++)
                #pragma unroll
                for (int c = 0; c < 4; c++) acc[mt][nt][c] = 0.0f;

        // ---- HMMA over K=128 ----
        #pragma unroll
        for (int kk = 0; kk < 128; kk += 16) {
            unsigned a[2][4], b[4][2];
            #pragma unroll
            for (int mt = 0; mt < 2; mt++) {
                const __half* p = As + aoff + mt * 16 * PA + kk;
                a[mt][0] = *(const unsigned*)(p);
                a[mt][1] = *(const unsigned*)(p + 8 * PA);
                a[mt][2] = *(const unsigned*)(p + 8);
                a[mt][3] = *(const unsigned*)(p + 8 * PA + 8);
            }
            #pragma unroll
            for (int nt = 0; nt < 4; nt++) {
                const __half* p = Bs + boff + nt * 8 * PA + kk;
                b[nt][0] = *(const unsigned*)(p);
                b[nt][1] = *(const unsigned*)(p + 8);
            }
            #pragma unroll
            for (int mt = 0; mt < 2; mt++)
                #pragma unroll
                for (int nt = 0; nt < 4; nt++)
                    asm volatile(
                        "mma.sync.aligned.m16n8k16.row.col.f32.f16.f16.f32 "
                        "{%0,%1,%2,%3}, {%4,%5,%6,%7}, {%8,%9}, {%0,%1,%2,%3};"
                        : "+f"(acc[mt][nt][0]), "+f"(acc[mt][nt][1]),
                          "+f"(acc[mt][nt][2]), "+f"(acc[mt][nt][3])
                        : "r"(a[mt][0]), "r"(a[mt][1]), "r"(a[mt][2]), "r"(a[mt][3]),
                          "r"(b[nt][0]), "r"(b[nt][1]));
        }

        // ---- h staging -> coalesced g_hh stores (warp-local) ----
        #pragma unroll
        for (int mt = 0; mt < 2; mt++)
            #pragma unroll
            for (int nt = 0; nt < 4; nt++) {
                int rl = mt * 16 + (lane >> 2);
                int cu = nt * 4 + (lane & 3);
                __half2 lo = __floats2half2_rn(acc[mt][nt][0], acc[mt][nt][1]);
                __half2 hi = __floats2half2_rn(acc[mt][nt][2], acc[mt][nt][3]);
                stg[rl * 20 + cu] = *reinterpret_cast<unsigned*>(&lo);
                stg[(rl + 8) * 20 + cu] = *reinterpret_cast<unsigned*>(&hi);
            }
        __syncwarp();
        #pragma unroll
        for (int it = 0; it < 4; it++) {
            int rl = it * 8 + (lane >> 2);
            uint4 v = *(uint4*)(stg + rl * 20 + (lane & 3) * 4);
            int grow = m_base + mw * 32 + rl;
            *(uint4*)(g_hh + (size_t)grow * 128 + head * 32 + nw * 16 +
                      (lane & 3) * 4) = v;
        }

        // ---- att logits from fp32 acc ----
        float s1v[2][2], s2v[2][2];
        #pragma unroll
        for (int mt = 0; mt < 2; mt++)
            #pragma unroll
            for (int half = 0; half < 2; half++) {
                float t1 = 0.f, t2 = 0.f;
                #pragma unroll
                for (int nt = 0; nt < 4; nt++)
                    #pragma unroll
                    for (int c2 = 0; c2 < 2; c2++) {
                        int col = head * 64 + nw * 32 + nt * 8 +
                                  (lane & 3) * 2 + c2;
                        float v = acc[mt][nt][half * 2 + c2];
                        t1 = fmaf(v, attv[col], t1);
                        t2 = fmaf(v, attv[256 + col], t2);
                    }
                t1 += __shfl_xor_sync(0xffffffffu, t1, 1);
                t1 += __shfl_xor_sync(0xffffffffu, t1, 2);
                t2 += __shfl_xor_sync(0xffffffffu, t2, 1);
                t2 += __shfl_xor_sync(0xffffffffu, t2, 2);
                s1v[mt][half] = t1;
                s2v[mt][half] = t2;
            }
        if (nw == 0 && (lane & 3) == 0) {
            #pragma unroll
            for (int mt = 0; mt < 2; mt++)
                #pragma unroll
                for (int half = 0; half < 2; half++) {
                    int rl = mw * 32 + mt * 16 + half * 8 + (lane >> 2);
                    red_s[rl] = s1v[mt][half];
                    red_d[rl] = s2v[mt][half];
                }
        }
        __syncthreads();
        if (nw == 1 && (lane & 3) == 0) {
            #pragma unroll
            for (int mt = 0; mt < 2; mt++)
                #pragma unroll
                for (int half = 0; half < 2; half++) {
                    int rl = mw * 32 + mt * 16 + half * 8 + (lane >> 2);
                    int row = m_base + rl;
                    if (row < N) {
                        ((float*)&g_asrc[row])[head] = s1v[mt][half] + red_s[rl];
                        ((float*)&g_adst[row])[head] = s2v[mt][half] + red_d[rl];
                    }
                }
        }
    }
}

// ---------------- 5: three-phase exclusive scan ----------------
__global__ void scan_a_kernel(int N) {
    __shared__ int sh[256];
    int idx = blockIdx.x * 256 + threadIdx.x;
    int v = (idx < N) ? g_cnt[idx] : 0;
    sh[threadIdx.x] = v;
    __syncthreads();
    #pragma unroll
    for (int off = 128; off >= 1; off >>= 1) {
        if (threadIdx.x < off) sh[threadIdx.x] += sh[threadIdx.x + off];
        __syncthreads();
    }
    if (threadIdx.x == 0) g_bsum[blockIdx.x] = sh[0];
}

__global__ void scan_b_kernel(int GB) {
    __shared__ int sh[256];
    int t = threadIdx.x;
    int v = (t < GB) ? g_bsum[t] : 0;
    sh[t] = v;
    __syncthreads();
    #pragma unroll
    for (int off = 1; off < 256; off <<= 1) {
        int u = (t >= off) ? sh[t - off] : 0;
        __syncthreads();
        sh[t] += u;
        __syncthreads();
    }
    g_boff[t] = sh[t] - v;
}

__global__ void scan_c_kernel(int N, int ET) {
    __shared__ int sh[256];
    int t = threadIdx.x;
    int idx = blockIdx.x * 256 + t;
    int c = (idx < N) ? g_cnt[idx] : 0;
    sh[t] = c;
    __syncthreads();
    #pragma unroll
    for (int off = 1; off < 256; off <<= 1) {
        int u = (t >= off) ? sh[t - off] : 0;
        __syncthreads();
        sh[t] += u;
        __syncthreads();
    }
    int ex = g_boff[blockIdx.x] + sh[t] - c;
    if (idx < N) {
        g_off[idx] = ex;
        g_cur[idx] = ex;
        if (idx == N - 1) g_off[N] = ET;
    }
}

// ---------------- 6: scatter (CSR fill, 4 edges/thread) ----------------
__global__ void scatter_kernel(const unsigned* __restrict__ w, int E, int N) {
    __shared__ int s_st;
    if (threadIdx.x == 0) s_st = edge_stride(w);
    __syncthreads();
    int st = s_st;
    int ET = E + N;
    int base = (blockIdx.x * blockDim.x + threadIdx.x) * 4;
    if (base >= ET) return;
    if (base + 4 <= ET) {
        int s[4], d[4];
        #pragma unroll
        for (int q = 0; q < 4; q++) {
            int i = base + q;
            if (i < E) {
                s[q] = (int)w[st * i];
                d[q] = (int)w[st * E + st * i];
            } else {
                s[q] = d[q] = i - E;
            }
        }
        #pragma unroll
        for (int q = 0; q < 4; q++) {
            int pos = atomicAdd(&g_cur[d[q]], 1);
            g_src[pos] = s[q];
        }
    } else {
        for (int i = base; i < ET; i++) {
            int s, d;
            if (i < E) {
                s = (int)w[st * i];
                d = (int)w[st * E + st * i];
            } else {
                s = d = i - E;
            }
            int pos = atomicAdd(&g_cur[d], 1);
            g_src[pos] = s;
        }
    }
}

// ---------------- 7: fused softmax + aggregate + bias + mix-ELU ------------
__device__ __forceinline__ float mixelu(float z) {
    float e = z > 0.0f ? z : expm1f(z);
    return 0.5f * z + 0.5f * e;
}

__global__ void __launch_bounds__(256)
agg_kernel(float* __restrict__ out, const float* __restrict__ bias, int N) {
    int gt = blockIdx.x * blockDim.x + threadIdx.x;
    int d = gt >> 5;
    int lane = gt & 31;
    if (d >= N) return;
    int beg = g_off[d], end = g_off[d + 1];
    int head = lane >> 3;                        // 8 features per lane
    bool hsel = (head & 1) != 0;
    bool hhi = head >= 2;

    float4 ad4 = g_adst[d];
    float ad = hhi ? (hsel ? ad4.w : ad4.z) : (hsel ? ad4.y : ad4.x);

    float acc[8] = {0.f, 0.f, 0.f, 0.f, 0.f, 0.f, 0.f, 0.f};
    float se = 0.f;

    #pragma unroll 2
    for (int j = beg; j < end; j++) {
        int s = __ldg(&g_src[j]);
        float4 as4 = __ldg(&g_asrc[s]);
        float as = hhi ? (hsel ? as4.w : as4.z) : (hsel ? as4.y : as4.x);
        float e = __expf(lrelu(as + ad));
        se += e;
        uint4 u = __ldg((const uint4*)(g_hh + (size_t)s * 128) + lane);
        float2 p0 = __half22float2(*reinterpret_cast<__half2*>(&u.x));
        float2 p1 = __half22float2(*reinterpret_cast<__half2*>(&u.y));
        float2 p2 = __half22float2(*reinterpret_cast<__half2*>(&u.z));
        float2 p3 = __half22float2(*reinterpret_cast<__half2*>(&u.w));
        acc[0] = fmaf(e, p0.x, acc[0]); acc[1] = fmaf(e, p0.y, acc[1]);
        acc[2] = fmaf(e, p1.x, acc[2]); acc[3] = fmaf(e, p1.y, acc[3]);
        acc[4] = fmaf(e, p2.x, acc[4]); acc[5] = fmaf(e, p2.y, acc[5]);
        acc[6] = fmaf(e, p3.x, acc[6]); acc[7] = fmaf(e, p3.y, acc[7]);
    }

    float inv = 1.0f / (se + 1e-16f);
    const float* brow = bias + lane * 8;
    float o[8];
    #pragma unroll
    for (int c = 0; c < 8; c++)
        o[c] = mixelu(acc[c] * inv + __ldg(brow + c));

    float4* orow = (float4*)(out + (size_t)d * FTOT);
    orow[lane * 2]     = make_float4(o[0], o[1], o[2], o[3]);
    orow[lane * 2 + 1] = make_float4(o[4], o[5], o[6], o[7]);
}

// ---------------- launch ----------------
extern "C" void kernel_launch(void* const* d_in, const int* in_sizes, int n_in,
                              void* d_out, int out_size) {
    const float*    x       = (const float*)d_in[0];
    const unsigned* edge    = (const unsigned*)d_in[1];
    const float*    W       = (const float*)d_in[2];
    const float*    att_src = (const float*)d_in[3];
    const float*    att_dst = (const float*)d_in[4];
    const float*    bias    = (const float*)d_in[5];
    float*          out     = (float*)d_out;

    const int N = in_sizes[0] / IN_DIM;        // 50000
    const int E = in_sizes[1] / 2;             // 800000
    const int ET = E + N;
    const int GB = (N + 255) / 256;

    cudaFuncSetAttribute(gemm_kernel,
                         cudaFuncAttributeMaxDynamicSharedMemorySize, SMEM_BYTES);

    zero_cnt_kernel<<<(N + 255) / 256, 256>>>(N);                     // 1
    hist_kernel<<<(ET + 1023) / 1024, 256>>>(edge, E, N);             // 2
    wt_kernel<<<128, 256>>>(W);                                       // 3
    gemm_kernel<<<(N + 127) / 128, 256, SMEM_BYTES>>>(x, att_src, att_dst, N); // 4
    scan_a_kernel<<<GB, 256>>>(N);                                    // 5
    scan_b_kernel<<<1, 256>>>(GB);                                    // 6
    scan_c_kernel<<<GB, 256>>>(N, ET);                                // 7
    scatter_kernel<<<(ET + 1023) / 1024, 256>>>(edge, E, N);          // 8
    agg_kernel<<<((long)N * 32 + 255) / 256, 256>>>(out, bias, N);    // 9
}

// round 12
// speedup vs baseline: 1.1365x; 1.0139x over previous
#include <cuda_runtime.h>
#include <cuda_bf16.h>
#include <cuda_fp16.h>
#include <cstdint>

#define MAXN 50048
#define MAXE 860032
#define IN_DIM 128
#define HEADS 4
#define OUT_DIM 64
#define FTOT 256

// ---------------- scratch ----------------
__device__ unsigned g_hh[(size_t)MAXN * 128];   // h as half2 pairs: 25.6 MB
__device__ float4 g_asrc[MAXN];
__device__ float4 g_adst[MAXN];
__device__ int    g_src[MAXE];
__device__ int    g_cnt[MAXN];
__device__ int    g_off[MAXN + 1];
__device__ int    g_cur[MAXN];
__device__ int    g_bsum[256];
__device__ int    g_boff[256];
__device__ __align__(16) __half g_wt[FTOT * IN_DIM];  // W^T fp16: [n][k]

__device__ __forceinline__ float lrelu(float e) {
    return e > 0.0f ? e : 0.2f * e;
}

__device__ __forceinline__ int edge_stride(const unsigned* w) {
    int is64 = 1;
    #pragma unroll 1
    for (int j = 1; j < 64; j += 2)
        if (w[j] != 0u) { is64 = 0; break; }
    return is64 ? 2 : 1;
}

// ---------------- 1: zero degree counters ----------------
__global__ void zero_cnt_kernel(int N) {
    int i = blockIdx.x * blockDim.x + threadIdx.x;
    if (i < N) g_cnt[i] = 0;
}

// ---------------- 2: histogram (4 edges/thread) ----------------
__global__ void hist_kernel(const unsigned* __restrict__ w, int E, int N) {
    __shared__ int s_st;
    if (threadIdx.x == 0) s_st = edge_stride(w);
    __syncthreads();
    int st = s_st;
    int ET = E + N;
    int base = (blockIdx.x * blockDim.x + threadIdx.x) * 4;
    if (base >= ET) return;
    if (base + 4 <= ET) {
        int d[4];
        #pragma unroll
        for (int q = 0; q < 4; q++) {
            int i = base + q;
            d[q] = (i < E) ? (int)w[st * E + st * i] : (i - E);
        }
        #pragma unroll
        for (int q = 0; q < 4; q++) atomicAdd(&g_cnt[d[q]], 1);
    } else {
        for (int i = base; i < ET; i++) {
            int d = (i < E) ? (int)w[st * E + st * i] : (i - E);
            atomicAdd(&g_cnt[d], 1);
        }
    }
}

// ---------------- 3: W transpose -> fp16 ----------------
__global__ void wt_kernel(const float* __restrict__ W) {
    int i = blockIdx.x * 256 + threadIdx.x;     // 0..32767
    int k = i & 127, n = i >> 7;
    g_wt[i] = __float2half_rn(__ldg(W + (size_t)k * FTOT + n));
}

// ---------------- 4: GEMM on fp16 HMMA, 4 heads/CTA, fused att logits -----
// Block: 256 thr (8 warps = 4m x 2n), A tile 128 x K=128 filled ONCE,
// loop over heads re-filling the 64x128 B tile. Epilogue staging OVERLAYS
// the B tile (dead between a head's MMA and the next head's fill) and the
// red arrays overlay staging -> total smem 57344 B = 4 CTAs/SM.
#define PA 136
#define SM_A 0                                   // 34816
#define SM_ATTV 34816                            // 2048 -> 36864
#define SM_B 36864                               // 17408 (B tile)
#define SM_STG 36864                             // 20480 (overlays B)
#define SM_RED 36864                             // 1024 (overlays stg warp0)
#define SMEM_BYTES 57344

__global__ void __launch_bounds__(256, 4)
gemm_kernel(const float* __restrict__ x,
            const float* __restrict__ att_src,
            const float* __restrict__ att_dst, int N) {
    extern __shared__ __align__(16) char sm[];
    __half* As = (__half*)(sm + SM_A);
    __half* Bs = (__half*)(sm + SM_B);
    float* attv  = (float*)(sm + SM_ATTV);       // [512]: src 0..255, dst 256..
    float* red_s = (float*)(sm + SM_RED);        // [128]
    float* red_d = red_s + 128;

    const int tid = threadIdx.x;
    const int lane = tid & 31, wid = tid >> 5;
    const int mw = wid & 3, nw = wid >> 2;
    const int m_base = blockIdx.x * 128;

    // preload att vectors (non-overlapped region, persists all heads)
    if (tid < 256) {
        attv[tid] = __ldg(att_src + tid);
        attv[256 + tid] = __ldg(att_dst + tid);
    }

    const int ar = tid >> 3;                    // 0..31 (row group)
    const int ac = tid & 7;                     // vec col idx

    // ---- A fill: 128 rows x 128 k -> fp16, coalesced, once ----
    #pragma unroll
    for (int rr = 0; rr < 4; rr++) {
        int r = ar + rr * 32;
        int grow = m_base + r;
        if (grow >= N) grow = N - 1;
        const float4* xs = (const float4*)(x + (size_t)grow * IN_DIM);
        #pragma unroll
        for (int p = 0; p < 4; p++) {
            float4 v = __ldg(xs + ac + p * 8);
            __half2 h0 = __floats2half2_rn(v.x, v.y);
            __half2 h1 = __floats2half2_rn(v.z, v.w);
            uint2 u;
            u.x = *reinterpret_cast<unsigned*>(&h0);
            u.y = *reinterpret_cast<unsigned*>(&h1);
            *(uint2*)(As + r * PA + (ac + p * 8) * 4) = u;
        }
    }

    const int aoff = (mw * 32 + (lane >> 2)) * PA + (lane & 3) * 2;
    const int boff = (nw * 32 + (lane >> 2)) * PA + (lane & 3) * 2;
    unsigned* stg = (unsigned*)(sm + SM_STG) + wid * (32 * 20);

    #pragma unroll 1
    for (int head = 0; head < HEADS; head++) {
        __syncthreads();                         // prev epilogue done; B writable
        // ---- B fill: 64 n-rows x 128 k for this head ----
        {
            int n = tid >> 2, q = tid & 3;
            const uint4* s = (const uint4*)(g_wt +
                (size_t)(head * OUT_DIM + n) * IN_DIM);
            uint4* dptr = (uint4*)(Bs + n * PA);
            #pragma unroll
            for (int j = 0; j < 4; j++)
                dptr[q * 4 + j] = __ldg(s + q * 4 + j);
        }
        __syncthreads();

        float acc[2][4][4];
        #pragma unroll
        for (int mt = 0; mt < 2; mt++)
            #pragma unroll
            for (int nt = 0; nt < 4; nt++)
                #pragma unroll
                for (int c = 0; c < 4; c++) acc[mt][nt][c] = 0.0f;

        // ---- HMMA over K=128 ----
        #pragma unroll
        for (int kk = 0; kk < 128; kk += 16) {
            unsigned a[2][4], b[4][2];
            #pragma unroll
            for (int mt = 0; mt < 2; mt++) {
                const __half* p = As + aoff + mt * 16 * PA + kk;
                a[mt][0] = *(const unsigned*)(p);
                a[mt][1] = *(const unsigned*)(p + 8 * PA);
                a[mt][2] = *(const unsigned*)(p + 8);
                a[mt][3] = *(const unsigned*)(p + 8 * PA + 8);
            }
            #pragma unroll
            for (int nt = 0; nt < 4; nt++) {
                const __half* p = Bs + boff + nt * 8 * PA + kk;
                b[nt][0] = *(const unsigned*)(p);
                b[nt][1] = *(const unsigned*)(p + 8);
            }
            #pragma unroll
            for (int mt = 0; mt < 2; mt++)
                #pragma unroll
                for (int nt = 0; nt < 4; nt++)
                    asm volatile(
                        "mma.sync.aligned.m16n8k16.row.col.f32.f16.f16.f32 "
                        "{%0,%1,%2,%3}, {%4,%5,%6,%7}, {%8,%9}, {%0,%1,%2,%3};"
                        : "+f"(acc[mt][nt][0]), "+f"(acc[mt][nt][1]),
                          "+f"(acc[mt][nt][2]), "+f"(acc[mt][nt][3])
                        : "r"(a[mt][0]), "r"(a[mt][1]), "r"(a[mt][2]), "r"(a[mt][3]),
                          "r"(b[nt][0]), "r"(b[nt][1]));
        }

        __syncthreads();                         // all Bs reads done; stg writable

        // ---- h staging (overlays Bs) -> coalesced g_hh stores ----
        #pragma unroll
        for (int mt = 0; mt < 2; mt++)
            #pragma unroll
            for (int nt = 0; nt < 4; nt++) {
                int rl = mt * 16 + (lane >> 2);
                int cu = nt * 4 + (lane & 3);
                __half2 lo = __floats2half2_rn(acc[mt][nt][0], acc[mt][nt][1]);
                __half2 hi = __floats2half2_rn(acc[mt][nt][2], acc[mt][nt][3]);
                stg[rl * 20 + cu] = *reinterpret_cast<unsigned*>(&lo);
                stg[(rl + 8) * 20 + cu] = *reinterpret_cast<unsigned*>(&hi);
            }
        __syncwarp();
        #pragma unroll
        for (int it = 0; it < 4; it++) {
            int rl = it * 8 + (lane >> 2);
            uint4 v = *(uint4*)(stg + rl * 20 + (lane & 3) * 4);
            int grow = m_base + mw * 32 + rl;
            *(uint4*)(g_hh + (size_t)grow * 128 + head * 32 + nw * 16 +
                      (lane & 3) * 4) = v;
        }

        // ---- att logits from fp32 acc ----
        float s1v[2][2], s2v[2][2];
        #pragma unroll
        for (int mt = 0; mt < 2; mt++)
            #pragma unroll
            for (int half = 0; half < 2; half++) {
                float t1 = 0.f, t2 = 0.f;
                #pragma unroll
                for (int nt = 0; nt < 4; nt++)
                    #pragma unroll
                    for (int c2 = 0; c2 < 2; c2++) {
                        int col = head * 64 + nw * 32 + nt * 8 +
                                  (lane & 3) * 2 + c2;
                        float v = acc[mt][nt][half * 2 + c2];
                        t1 = fmaf(v, attv[col], t1);
                        t2 = fmaf(v, attv[256 + col], t2);
                    }
                t1 += __shfl_xor_sync(0xffffffffu, t1, 1);
                t1 += __shfl_xor_sync(0xffffffffu, t1, 2);
                t2 += __shfl_xor_sync(0xffffffffu, t2, 1);
                t2 += __shfl_xor_sync(0xffffffffu, t2, 2);
                s1v[mt][half] = t1;
                s2v[mt][half] = t2;
            }
        __syncthreads();                         // all stg reads done; red writable
        if (nw == 0 && (lane & 3) == 0) {
            #pragma unroll
            for (int mt = 0; mt < 2; mt++)
                #pragma unroll
                for (int half = 0; half < 2; half++) {
                    int rl = mw * 32 + mt * 16 + half * 8 + (lane >> 2);
                    red_s[rl] = s1v[mt][half];
                    red_d[rl] = s2v[mt][half];
                }
        }
        __syncthreads();
        if (nw == 1 && (lane & 3) == 0) {
            #pragma unroll
            for (int mt = 0; mt < 2; mt++)
                #pragma unroll
                for (int half = 0; half < 2; half++) {
                    int rl = mw * 32 + mt * 16 + half * 8 + (lane >> 2);
                    int row = m_base + rl;
                    if (row < N) {
                        ((float*)&g_asrc[row])[head] = s1v[mt][half] + red_s[rl];
                        ((float*)&g_adst[row])[head] = s2v[mt][half] + red_d[rl];
                    }
                }
        }
    }
}

// ---------------- 5: three-phase exclusive scan ----------------
__global__ void scan_a_kernel(int N) {
    __shared__ int sh[256];
    int idx = blockIdx.x * 256 + threadIdx.x;
    int v = (idx < N) ? g_cnt[idx] : 0;
    sh[threadIdx.x] = v;
    __syncthreads();
    #pragma unroll
    for (int off = 128; off >= 1; off >>= 1) {
        if (threadIdx.x < off) sh[threadIdx.x] += sh[threadIdx.x + off];
        __syncthreads();
    }
    if (threadIdx.x == 0) g_bsum[blockIdx.x] = sh[0];
}

__global__ void scan_b_kernel(int GB) {
    __shared__ int sh[256];
    int t = threadIdx.x;
    int v = (t < GB) ? g_bsum[t] : 0;
    sh[t] = v;
    __syncthreads();
    #pragma unroll
    for (int off = 1; off < 256; off <<= 1) {
        int u = (t >= off) ? sh[t - off] : 0;
        __syncthreads();
        sh[t] += u;
        __syncthreads();
    }
    g_boff[t] = sh[t] - v;
}

__global__ void scan_c_kernel(int N, int ET) {
    __shared__ int sh[256];
    int t = threadIdx.x;
    int idx = blockIdx.x * 256 + t;
    int c = (idx < N) ? g_cnt[idx] : 0;
    sh[t] = c;
    __syncthreads();
    #pragma unroll
    for (int off = 1; off < 256; off <<= 1) {
        int u = (t >= off) ? sh[t - off] : 0;
        __syncthreads();
        sh[t] += u;
        __syncthreads();
    }
    int ex = g_boff[blockIdx.x] + sh[t] - c;
    if (idx < N) {
        g_off[idx] = ex;
        g_cur[idx] = ex;
        if (idx == N - 1) g_off[N] = ET;
    }
}

// ---------------- 6: scatter (CSR fill, 4 edges/thread) ----------------
__global__ void scatter_kernel(const unsigned* __restrict__ w, int E, int N) {
    __shared__ int s_st;
    if (threadIdx.x == 0) s_st = edge_stride(w);
    __syncthreads();
    int st = s_st;
    int ET = E + N;
    int base = (blockIdx.x * blockDim.x + threadIdx.x) * 4;
    if (base >= ET) return;
    if (base + 4 <= ET) {
        int s[4], d[4];
        #pragma unroll
        for (int q = 0; q < 4; q++) {
            int i = base + q;
            if (i < E) {
                s[q] = (int)w[st * i];
                d[q] = (int)w[st * E + st * i];
            } else {
                s[q] = d[q] = i - E;
            }
        }
        #pragma unroll
        for (int q = 0; q < 4; q++) {
            int pos = atomicAdd(&g_cur[d[q]], 1);
            g_src[pos] = s[q];
        }
    } else {
        for (int i = base; i < ET; i++) {
            int s, d;
            if (i < E) {
                s = (int)w[st * i];
                d = (int)w[st * E + st * i];
            } else {
                s = d = i - E;
            }
            int pos = atomicAdd(&g_cur[d], 1);
            g_src[pos] = s;
        }
    }
}

// ---------------- 7: fused softmax + aggregate + bias + mix-ELU ------------
__device__ __forceinline__ float mixelu(float z) {
    float e = z > 0.0f ? z : expm1f(z);
    return 0.5f * z + 0.5f * e;
}

__global__ void __launch_bounds__(256)
agg_kernel(float* __restrict__ out, const float* __restrict__ bias, int N) {
    int gt = blockIdx.x * blockDim.x + threadIdx.x;
    int d = gt >> 5;
    int lane = gt & 31;
    if (d >= N) return;
    int beg = g_off[d], end = g_off[d + 1];
    int head = lane >> 3;                        // 8 features per lane
    bool hsel = (head & 1) != 0;
    bool hhi = head >= 2;

    float4 ad4 = g_adst[d];
    float ad = hhi ? (hsel ? ad4.w : ad4.z) : (hsel ? ad4.y : ad4.x);

    float acc[8] = {0.f, 0.f, 0.f, 0.f, 0.f, 0.f, 0.f, 0.f};
    float se = 0.f;

    #pragma unroll 2
    for (int j = beg; j < end; j++) {
        int s = __ldcs(&g_src[j]);               // read-once: evict-first
        float4 as4 = __ldg(&g_asrc[s]);
        float as = hhi ? (hsel ? as4.w : as4.z) : (hsel ? as4.y : as4.x);
        float e = __expf(lrelu(as + ad));
        se += e;
        uint4 u = __ldg((const uint4*)(g_hh + (size_t)s * 128) + lane);
        float2 p0 = __half22float2(*reinterpret_cast<__half2*>(&u.x));
        float2 p1 = __half22float2(*reinterpret_cast<__half2*>(&u.y));
        float2 p2 = __half22float2(*reinterpret_cast<__half2*>(&u.z));
        float2 p3 = __half22float2(*reinterpret_cast<__half2*>(&u.w));
        acc[0] = fmaf(e, p0.x, acc[0]); acc[1] = fmaf(e, p0.y, acc[1]);
        acc[2] = fmaf(e, p1.x, acc[2]); acc[3] = fmaf(e, p1.y, acc[3]);
        acc[4] = fmaf(e, p2.x, acc[4]); acc[5] = fmaf(e, p2.y, acc[5]);
        acc[6] = fmaf(e, p3.x, acc[6]); acc[7] = fmaf(e, p3.y, acc[7]);
    }

    float inv = 1.0f / (se + 1e-16f);
    const float* brow = bias + lane * 8;
    float o[8];
    #pragma unroll
    for (int c = 0; c < 8; c++)
        o[c] = mixelu(acc[c] * inv + __ldg(brow + c));

    float4* orow = (float4*)(out + (size_t)d * FTOT);
    __stcs(orow + lane * 2,     make_float4(o[0], o[1], o[2], o[3]));
    __stcs(orow + lane * 2 + 1, make_float4(o[4], o[5], o[6], o[7]));
}

// ---------------- launch ----------------
extern "C" void kernel_launch(void* const* d_in, const int* in_sizes, int n_in,
                              void* d_out, int out_size) {
    const float*    x       = (const float*)d_in[0];
    const unsigned* edge    = (const unsigned*)d_in[1];
    const float*    W       = (const float*)d_in[2];
    const float*    att_src = (const float*)d_in[3];
    const float*    att_dst = (const float*)d_in[4];
    const float*    bias    = (const float*)d_in[5];
    float*          out     = (float*)d_out;

    const int N = in_sizes[0] / IN_DIM;        // 50000
    const int E = in_sizes[1] / 2;             // 800000
    const int ET = E + N;
    const int GB = (N + 255) / 256;

    cudaFuncSetAttribute(gemm_kernel,
                         cudaFuncAttributeMaxDynamicSharedMemorySize, SMEM_BYTES);

    zero_cnt_kernel<<<(N + 255) / 256, 256>>>(N);                     // 1
    hist_kernel<<<(ET + 1023) / 1024, 256>>>(edge, E, N);             // 2
    wt_kernel<<<128, 256>>>(W);                                       // 3
    gemm_kernel<<<(N + 127) / 128, 256, SMEM_BYTES>>>(x, att_src, att_dst, N); // 4
    scan_a_kernel<<<GB, 256>>>(N);                                    // 5
    scan_b_kernel<<<1, 256>>>(GB);                                    // 6
    scan_c_kernel<<<GB, 256>>>(N, ET);                                // 7
    scatter_kernel<<<(ET + 1023) / 1024, 256>>>(edge, E, N);          // 8
    agg_kernel<<<((long)N * 32 + 255) / 256, 256>>>(out, bias, N);    // 9
}

// round 13
// speedup vs baseline: 1.1854x; 1.0430x over previous
#include <cuda_runtime.h>
#include <cuda_bf16.h>
#include <cuda_fp16.h>
#include <cstdint>

#define MAXN 50048
#define MAXE 860032
#define IN_DIM 128
#define HEADS 4
#define OUT_DIM 64
#define FTOT 256

// ---------------- scratch ----------------
__device__ unsigned g_hh[(size_t)MAXN * 128];   // h as half2 pairs: 25.6 MB
__device__ float4 g_asrc[MAXN];
__device__ float4 g_adst[MAXN];
__device__ int    g_src[MAXE];
__device__ int    g_cnt[MAXN];
__device__ int    g_off[MAXN + 1];
__device__ int    g_cur[MAXN];
__device__ int    g_bsum[256];
__device__ int    g_boff[256];
__device__ __align__(16) __half g_wt[FTOT * IN_DIM];  // W^T fp16: [n][k]

__device__ __forceinline__ float lrelu(float e) {
    return e > 0.0f ? e : 0.2f * e;
}

__device__ __forceinline__ int edge_stride(const unsigned* w) {
    int is64 = 1;
    #pragma unroll 1
    for (int j = 1; j < 64; j += 2)
        if (w[j] != 0u) { is64 = 0; break; }
    return is64 ? 2 : 1;
}

// ---------------- 1: zero degree counters ----------------
__global__ void zero_cnt_kernel(int N) {
    int i = blockIdx.x * blockDim.x + threadIdx.x;
    if (i < N) g_cnt[i] = 0;
}

// ---------------- 2: histogram (4 edges/thread) ----------------
__global__ void hist_kernel(const unsigned* __restrict__ w, int E, int N) {
    __shared__ int s_st;
    if (threadIdx.x == 0) s_st = edge_stride(w);
    __syncthreads();
    int st = s_st;
    int ET = E + N;
    int base = (blockIdx.x * blockDim.x + threadIdx.x) * 4;
    if (base >= ET) return;
    if (base + 4 <= ET) {
        int d[4];
        #pragma unroll
        for (int q = 0; q < 4; q++) {
            int i = base + q;
            d[q] = (i < E) ? (int)w[st * E + st * i] : (i - E);
        }
        #pragma unroll
        for (int q = 0; q < 4; q++) atomicAdd(&g_cnt[d[q]], 1);
    } else {
        for (int i = base; i < ET; i++) {
            int d = (i < E) ? (int)w[st * E + st * i] : (i - E);
            atomicAdd(&g_cnt[d], 1);
        }
    }
}

// ---------------- 3: W transpose -> fp16 ----------------
__global__ void wt_kernel(const float* __restrict__ W) {
    int i = blockIdx.x * 256 + threadIdx.x;     // 0..32767
    int k = i & 127, n = i >> 7;
    g_wt[i] = __float2half_rn(__ldg(W + (size_t)k * FTOT + n));
}

// ---------------- 4: GEMM on fp16 HMMA, 4 heads/CTA, fused att logits -----
#define PA 136
#define SM_A 0                                   // 34816
#define SM_ATTV 34816                            // 2048 -> 36864
#define SM_B 36864                               // 17408 (B tile)
#define SM_STG 36864                             // 20480 (overlays B)
#define SM_RED 36864                             // 1024 (overlays stg warp0)
#define SMEM_BYTES 57344

__global__ void __launch_bounds__(256, 4)
gemm_kernel(const float* __restrict__ x,
            const float* __restrict__ att_src,
            const float* __restrict__ att_dst, int N) {
    extern __shared__ __align__(16) char sm[];
    __half* As = (__half*)(sm + SM_A);
    __half* Bs = (__half*)(sm + SM_B);
    float* attv  = (float*)(sm + SM_ATTV);       // [512]: src 0..255, dst 256..
    float* red_s = (float*)(sm + SM_RED);        // [128]
    float* red_d = red_s + 128;

    const int tid = threadIdx.x;
    const int lane = tid & 31, wid = tid >> 5;
    const int mw = wid & 3, nw = wid >> 2;
    const int m_base = blockIdx.x * 128;

    if (tid < 256) {
        attv[tid] = __ldg(att_src + tid);
        attv[256 + tid] = __ldg(att_dst + tid);
    }

    const int ar = tid >> 3;
    const int ac = tid & 7;

    // ---- A fill: 128 rows x 128 k -> fp16, coalesced, once ----
    #pragma unroll
    for (int rr = 0; rr < 4; rr++) {
        int r = ar + rr * 32;
        int grow = m_base + r;
        if (grow >= N) grow = N - 1;
        const float4* xs = (const float4*)(x + (size_t)grow * IN_DIM);
        #pragma unroll
        for (int p = 0; p < 4; p++) {
            float4 v = __ldg(xs + ac + p * 8);
            __half2 h0 = __floats2half2_rn(v.x, v.y);
            __half2 h1 = __floats2half2_rn(v.z, v.w);
            uint2 u;
            u.x = *reinterpret_cast<unsigned*>(&h0);
            u.y = *reinterpret_cast<unsigned*>(&h1);
            *(uint2*)(As + r * PA + (ac + p * 8) * 4) = u;
        }
    }

    const int aoff = (mw * 32 + (lane >> 2)) * PA + (lane & 3) * 2;
    const int boff = (nw * 32 + (lane >> 2)) * PA + (lane & 3) * 2;
    unsigned* stg = (unsigned*)(sm + SM_STG) + wid * (32 * 20);

    #pragma unroll 1
    for (int head = 0; head < HEADS; head++) {
        __syncthreads();
        // ---- B fill: 64 n-rows x 128 k for this head ----
        {
            int n = tid >> 2, q = tid & 3;
            const uint4* s = (const uint4*)(g_wt +
                (size_t)(head * OUT_DIM + n) * IN_DIM);
            uint4* dptr = (uint4*)(Bs + n * PA);
            #pragma unroll
            for (int j = 0; j < 4; j++)
                dptr[q * 4 + j] = __ldg(s + q * 4 + j);
        }
        __syncthreads();

        float acc[2][4][4];
        #pragma unroll
        for (int mt = 0; mt < 2; mt++)
            #pragma unroll
            for (int nt = 0; nt < 4; nt++)
                #pragma unroll
                for (int c = 0; c < 4; c++) acc[mt][nt][c] = 0.0f;

        // ---- HMMA over K=128 ----
        #pragma unroll
        for (int kk = 0; kk < 128; kk += 16) {
            unsigned a[2][4], b[4][2];
            #pragma unroll
            for (int mt = 0; mt < 2; mt++) {
                const __half* p = As + aoff + mt * 16 * PA + kk;
                a[mt][0] = *(const unsigned*)(p);
                a[mt][1] = *(const unsigned*)(p + 8 * PA);
                a[mt][2] = *(const unsigned*)(p + 8);
                a[mt][3] = *(const unsigned*)(p + 8 * PA + 8);
            }
            #pragma unroll
            for (int nt = 0; nt < 4; nt++) {
                const __half* p = Bs + boff + nt * 8 * PA + kk;
                b[nt][0] = *(const unsigned*)(p);
                b[nt][1] = *(const unsigned*)(p + 8);
            }
            #pragma unroll
            for (int mt = 0; mt < 2; mt++)
                #pragma unroll
                for (int nt = 0; nt < 4; nt++)
                    asm volatile(
                        "mma.sync.aligned.m16n8k16.row.col.f32.f16.f16.f32 "
                        "{%0,%1,%2,%3}, {%4,%5,%6,%7}, {%8,%9}, {%0,%1,%2,%3};"
                        : "+f"(acc[mt][nt][0]), "+f"(acc[mt][nt][1]),
                          "+f"(acc[mt][nt][2]), "+f"(acc[mt][nt][3])
                        : "r"(a[mt][0]), "r"(a[mt][1]), "r"(a[mt][2]), "r"(a[mt][3]),
                          "r"(b[nt][0]), "r"(b[nt][1]));
        }

        __syncthreads();

        // ---- h staging (overlays Bs) -> coalesced g_hh stores ----
        #pragma unroll
        for (int mt = 0; mt < 2; mt++)
            #pragma unroll
            for (int nt = 0; nt < 4; nt++) {
                int rl = mt * 16 + (lane >> 2);
                int cu = nt * 4 + (lane & 3);
                __half2 lo = __floats2half2_rn(acc[mt][nt][0], acc[mt][nt][1]);
                __half2 hi = __floats2half2_rn(acc[mt][nt][2], acc[mt][nt][3]);
                stg[rl * 20 + cu] = *reinterpret_cast<unsigned*>(&lo);
                stg[(rl + 8) * 20 + cu] = *reinterpret_cast<unsigned*>(&hi);
            }
        __syncwarp();
        #pragma unroll
        for (int it = 0; it < 4; it++) {
            int rl = it * 8 + (lane >> 2);
            uint4 v = *(uint4*)(stg + rl * 20 + (lane & 3) * 4);
            int grow = m_base + mw * 32 + rl;
            *(uint4*)(g_hh + (size_t)grow * 128 + head * 32 + nw * 16 +
                      (lane & 3) * 4) = v;
        }

        // ---- att logits from fp32 acc ----
        float s1v[2][2], s2v[2][2];
        #pragma unroll
        for (int mt = 0; mt < 2; mt++)
            #pragma unroll
            for (int half = 0; half < 2; half++) {
                float t1 = 0.f, t2 = 0.f;
                #pragma unroll
                for (int nt = 0; nt < 4; nt++)
                    #pragma unroll
                    for (int c2 = 0; c2 < 2; c2++) {
                        int col = head * 64 + nw * 32 + nt * 8 +
                                  (lane & 3) * 2 + c2;
                        float v = acc[mt][nt][half * 2 + c2];
                        t1 = fmaf(v, attv[col], t1);
                        t2 = fmaf(v, attv[256 + col], t2);
                    }
                t1 += __shfl_xor_sync(0xffffffffu, t1, 1);
                t1 += __shfl_xor_sync(0xffffffffu, t1, 2);
                t2 += __shfl_xor_sync(0xffffffffu, t2, 1);
                t2 += __shfl_xor_sync(0xffffffffu, t2, 2);
                s1v[mt][half] = t1;
                s2v[mt][half] = t2;
            }
        __syncthreads();
        if (nw == 0 && (lane & 3) == 0) {
            #pragma unroll
            for (int mt = 0; mt < 2; mt++)
                #pragma unroll
                for (int half = 0; half < 2; half++) {
                    int rl = mw * 32 + mt * 16 + half * 8 + (lane >> 2);
                    red_s[rl] = s1v[mt][half];
                    red_d[rl] = s2v[mt][half];
                }
        }
        __syncthreads();
        if (nw == 1 && (lane & 3) == 0) {
            #pragma unroll
            for (int mt = 0; mt < 2; mt++)
                #pragma unroll
                for (int half = 0; half < 2; half++) {
                    int rl = mw * 32 + mt * 16 + half * 8 + (lane >> 2);
                    int row = m_base + rl;
                    if (row < N) {
                        ((float*)&g_asrc[row])[head] = s1v[mt][half] + red_s[rl];
                        ((float*)&g_adst[row])[head] = s2v[mt][half] + red_d[rl];
                    }
                }
        }
    }
}

// ---------------- 5: three-phase exclusive scan ----------------
__global__ void scan_a_kernel(int N) {
    __shared__ int sh[256];
    int idx = blockIdx.x * 256 + threadIdx.x;
    int v = (idx < N) ? g_cnt[idx] : 0;
    sh[threadIdx.x] = v;
    __syncthreads();
    #pragma unroll
    for (int off = 128; off >= 1; off >>= 1) {
        if (threadIdx.x < off) sh[threadIdx.x] += sh[threadIdx.x + off];
        __syncthreads();
    }
    if (threadIdx.x == 0) g_bsum[blockIdx.x] = sh[0];
}

__global__ void scan_b_kernel(int GB) {
    __shared__ int sh[256];
    int t = threadIdx.x;
    int v = (t < GB) ? g_bsum[t] : 0;
    sh[t] = v;
    __syncthreads();
    #pragma unroll
    for (int off = 1; off < 256; off <<= 1) {
        int u = (t >= off) ? sh[t - off] : 0;
        __syncthreads();
        sh[t] += u;
        __syncthreads();
    }
    g_boff[t] = sh[t] - v;
}

__global__ void scan_c_kernel(int N, int ET) {
    __shared__ int sh[256];
    int t = threadIdx.x;
    int idx = blockIdx.x * 256 + t;
    int c = (idx < N) ? g_cnt[idx] : 0;
    sh[t] = c;
    __syncthreads();
    #pragma unroll
    for (int off = 1; off < 256; off <<= 1) {
        int u = (t >= off) ? sh[t - off] : 0;
        __syncthreads();
        sh[t] += u;
        __syncthreads();
    }
    int ex = g_boff[blockIdx.x] + sh[t] - c;
    if (idx < N) {
        g_off[idx] = ex;
        g_cur[idx] = ex;
        if (idx == N - 1) g_off[N] = ET;
    }
}

// ---------------- 6: scatter (CSR fill, 4 edges/thread) ----------------
__global__ void scatter_kernel(const unsigned* __restrict__ w, int E, int N) {
    __shared__ int s_st;
    if (threadIdx.x == 0) s_st = edge_stride(w);
    __syncthreads();
    int st = s_st;
    int ET = E + N;
    int base = (blockIdx.x * blockDim.x + threadIdx.x) * 4;
    if (base >= ET) return;
    if (base + 4 <= ET) {
        int s[4], d[4];
        #pragma unroll
        for (int q = 0; q < 4; q++) {
            int i = base + q;
            if (i < E) {
                s[q] = (int)w[st * i];
                d[q] = (int)w[st * E + st * i];
            } else {
                s[q] = d[q] = i - E;
            }
        }
        #pragma unroll
        for (int q = 0; q < 4; q++) {
            int pos = atomicAdd(&g_cur[d[q]], 1);
            g_src[pos] = s[q];
        }
    } else {
        for (int i = base; i < ET; i++) {
            int s, d;
            if (i < E) {
                s = (int)w[st * i];
                d = (int)w[st * E + st * i];
            } else {
                s = d = i - E;
            }
            int pos = atomicAdd(&g_cur[d], 1);
            g_src[pos] = s;
        }
    }
}

// ---------------- 7: fused softmax + aggregate + bias + mix-ELU ------------
__device__ __forceinline__ float mixelu(float z) {
    float e = z > 0.0f ? z : expm1f(z);
    return 0.5f * z + 0.5f * e;
}

__global__ void __launch_bounds__(256)
agg_kernel(float* __restrict__ out, const float* __restrict__ bias, int N) {
    int gt = blockIdx.x * blockDim.x + threadIdx.x;
    int d = gt >> 5;
    int lane = gt & 31;
    if (d >= N) return;
    int beg = g_off[d], end = g_off[d + 1];
    int head = lane >> 3;
    bool hsel = (head & 1) != 0;
    bool hhi = head >= 2;

    float4 ad4 = g_adst[d];
    float ad = hhi ? (hsel ? ad4.w : ad4.z) : (hsel ? ad4.y : ad4.x);

    float acc[8] = {0.f, 0.f, 0.f, 0.f, 0.f, 0.f, 0.f, 0.f};
    float se = 0.f;

    #pragma unroll 2
    for (int j = beg; j < end; j++) {
        int s = __ldcs(&g_src[j]);
        float4 as4 = __ldg(&g_asrc[s]);
        float as = hhi ? (hsel ? as4.w : as4.z) : (hsel ? as4.y : as4.x);
        float e = __expf(lrelu(as + ad));
        se += e;
        uint4 u = __ldg((const uint4*)(g_hh + (size_t)s * 128) + lane);
        float2 p0 = __half22float2(*reinterpret_cast<__half2*>(&u.x));
        float2 p1 = __half22float2(*reinterpret_cast<__half2*>(&u.y));
        float2 p2 = __half22float2(*reinterpret_cast<__half2*>(&u.z));
        float2 p3 = __half22float2(*reinterpret_cast<__half2*>(&u.w));
        acc[0] = fmaf(e, p0.x, acc[0]); acc[1] = fmaf(e, p0.y, acc[1]);
        acc[2] = fmaf(e, p1.x, acc[2]); acc[3] = fmaf(e, p1.y, acc[3]);
        acc[4] = fmaf(e, p2.x, acc[4]); acc[5] = fmaf(e, p2.y, acc[5]);
        acc[6] = fmaf(e, p3.x, acc[6]); acc[7] = fmaf(e, p3.y, acc[7]);
    }

    float inv = 1.0f / (se + 1e-16f);
    const float* brow = bias + lane * 8;
    float o[8];
    #pragma unroll
    for (int c = 0; c < 8; c++)
        o[c] = mixelu(acc[c] * inv + __ldg(brow + c));

    float4* orow = (float4*)(out + (size_t)d * FTOT);
    __stcs(orow + lane * 2,     make_float4(o[0], o[1], o[2], o[3]));
    __stcs(orow + lane * 2 + 1, make_float4(o[4], o[5], o[6], o[7]));
}

// ---------------- launch: fork-join across two side streams ----------------
extern "C" void kernel_launch(void* const* d_in, const int* in_sizes, int n_in,
                              void* d_out, int out_size) {
    const float*    x       = (const float*)d_in[0];
    const unsigned* edge    = (const unsigned*)d_in[1];
    const float*    W       = (const float*)d_in[2];
    const float*    att_src = (const float*)d_in[3];
    const float*    att_dst = (const float*)d_in[4];
    const float*    bias    = (const float*)d_in[5];
    float*          out     = (float*)d_out;

    const int N = in_sizes[0] / IN_DIM;        // 50000
    const int E = in_sizes[1] / 2;             // 800000
    const int ET = E + N;
    const int GB = (N + 255) / 256;

    static cudaStream_t s1 = nullptr, s2 = nullptr;
    static cudaEvent_t e0 = nullptr, e1 = nullptr, e2 = nullptr;
    if (s1 == nullptr) {
        cudaStreamCreateWithFlags(&s1, cudaStreamNonBlocking);
        cudaStreamCreateWithFlags(&s2, cudaStreamNonBlocking);
        cudaEventCreateWithFlags(&e0, cudaEventDisableTiming);
        cudaEventCreateWithFlags(&e1, cudaEventDisableTiming);
        cudaEventCreateWithFlags(&e2, cudaEventDisableTiming);
        cudaFuncSetAttribute(gemm_kernel,
                             cudaFuncAttributeMaxDynamicSharedMemorySize,
                             SMEM_BYTES);
    }

    // fork from the capture-origin (default) stream
    cudaEventRecord(e0, 0);
    cudaStreamWaitEvent(s1, e0, 0);
    cudaStreamWaitEvent(s2, e0, 0);

    // branch 1: feature pipeline (x, W)
    wt_kernel<<<128, 256, 0, s1>>>(W);
    gemm_kernel<<<(N + 127) / 128, 256, SMEM_BYTES, s1>>>(x, att_src, att_dst, N);
    cudaEventRecord(e1, s1);

    // branch 2: edge/CSR pipeline
    zero_cnt_kernel<<<(N + 255) / 256, 256, 0, s2>>>(N);
    hist_kernel<<<(ET + 1023) / 1024, 256, 0, s2>>>(edge, E, N);
    scan_a_kernel<<<GB, 256, 0, s2>>>(N);
    scan_b_kernel<<<1, 256, 0, s2>>>(GB);
    scan_c_kernel<<<GB, 256, 0, s2>>>(N, ET);
    scatter_kernel<<<(ET + 1023) / 1024, 256, 0, s2>>>(edge, E, N);
    cudaEventRecord(e2, s2);

    // join on the origin stream, then aggregate
    cudaStreamWaitEvent(0, e1, 0);
    cudaStreamWaitEvent(0, e2, 0);
    agg_kernel<<<((long)N * 32 + 255) / 256, 256>>>(out, bias, N);
}